// round 3
// baseline (speedup 1.0000x reference)
#include <cuda_runtime.h>
#include <cstdint>
#include <math.h>

#define BATCH 64
#define NN    1024
#define DD    16

#define THREADS 256
#define WARPS   8
#define ROWS    32      // rows per CTA, lane = row
#define JH      512     // j-columns per CTA (half of N)
#define JWARP   64      // j-window per warp
#define JT      16      // j-tile staged through smem
#define NTILES  (JWARP / JT)
#define RP      34      // transposed-tile pitch: 4*RP mod 32 == 8 -> conflict-free

// smem (floats)
#define SF_FLOATS   (JH * DD)                 // 8192 (32KB)
#define SAT_OFF     SF_FLOATS
#define SAT_FLOATS  (WARPS * JT * RP)         // 4352 (17KB)
#define SDEG_OFF    (SAT_OFF + SAT_FLOATS)
#define SC_OFF      (SDEG_OFF + ROWS * 9)
#define SMEM_FLOATS (SC_OFF + ROWS * 9)
#define SMEM_BYTES  (SMEM_FLOATS * 4)         // ~52.5KB -> 4 CTAs/SM

__device__ float g_deg[BATCH][NN][2];         // per-(b,n) degree halves

// ---------------- packed f32x2 helpers ----------------
__device__ __forceinline__ unsigned long long pk2(float a, float b) {
    unsigned long long r;
    asm("mov.b64 %0, {%1, %2};" : "=l"(r) : "f"(a), "f"(b));
    return r;
}
__device__ __forceinline__ void upk2(unsigned long long v, float& a, float& b) {
    asm("mov.b64 {%0, %1}, %2;" : "=f"(a), "=f"(b) : "l"(v));
}
__device__ __forceinline__ unsigned long long fma2(unsigned long long a,
                                                   unsigned long long b,
                                                   unsigned long long c) {
    unsigned long long d;
    asm("fma.rn.f32x2 %0, %1, %2, %3;" : "=l"(d) : "l"(a), "l"(b), "l"(c));
    return d;
}
__device__ __forceinline__ unsigned long long add2(unsigned long long a,
                                                   unsigned long long b) {
    unsigned long long d;
    asm("add.rn.f32x2 %0, %1, %2;" : "=l"(d) : "l"(a), "l"(b));
    return d;
}

__global__ void zero_out_kernel(float* out) {
    if (threadIdx.x < BATCH) out[threadIdx.x] = 0.0f;
}

__global__ void __launch_bounds__(THREADS, 4)
graph_loss_main(const float* __restrict__ A,
                const float* __restrict__ Fm,
                float* __restrict__ out) {
    extern __shared__ float sm[];
    float* sF   = sm;
    float* sDeg = sm + SDEG_OFF;
    float* sC   = sm + SC_OFF;

    const int b    = blockIdx.z;
    const int half = blockIdx.y;
    const int n0   = blockIdx.x * ROWS;
    const int tid  = threadIdx.x;
    const int w    = tid >> 5;
    const int lane = tid & 31;

    // ---- load F[b] j-half into shared (coalesced float4) ----
    {
        const float4* Fg  = (const float4*)(Fm + ((size_t)b * NN + (size_t)half * JH) * DD);
        float4*       sF4 = (float4*)sF;
        #pragma unroll
        for (int i = 0; i < (SF_FLOATS / 4) / THREADS; i++)
            sF4[tid + i * THREADS] = Fg[tid + i * THREADS];
    }
    __syncthreads();

    float* myAT   = sm + SAT_OFF + w * (JT * RP);
    float* atBase = myAT + lane;                 // lane = row index

    const int rbase = lane >> 2;                 // 0..7
    const int sub   = lane & 3;                  // 0..3
    const int jb    = sub * 4;

    const float* Aw = A + ((size_t)b * NN + n0) * NN + (size_t)half * JH + (size_t)w * JWARP;

    unsigned long long af[8];
    #pragma unroll
    for (int q = 0; q < 8; q++) af[q] = 0ull;
    unsigned long long deg2 = 0ull, ss2 = 0ull;

    float4 pf[4];
    #pragma unroll
    for (int s = 0; s < 4; s++) {
        int r = 8 * s + rbase;
        pf[s] = *(const float4*)(Aw + (size_t)r * NN + jb);
    }

    const float* sFw = sF + (w * JWARP) * DD;

    #pragma unroll 1
    for (int t = 0; t < NTILES; t++) {
        // stage transposed tile (conflict-free: bank = 8*sub + rbase + 2k)
        #pragma unroll
        for (int s = 0; s < 4; s++) {
            int r = 8 * s + rbase;
            myAT[(jb + 0) * RP + r] = pf[s].x;
            myAT[(jb + 1) * RP + r] = pf[s].y;
            myAT[(jb + 2) * RP + r] = pf[s].z;
            myAT[(jb + 3) * RP + r] = pf[s].w;
        }
        __syncwarp();

        if (t + 1 < NTILES) {
            const float* Anext = Aw + (t + 1) * JT;
            #pragma unroll
            for (int s = 0; s < 4; s++) {
                int r = 8 * s + rbase;
                pf[s] = *(const float4*)(Anext + (size_t)r * NN + jb);
            }
        }

        const float* fT = sFw + (t * JT) * DD;
        #pragma unroll
        for (int jp = 0; jp < 8; jp++) {
            const int j0 = 2 * jp;
            float a0 = atBase[j0 * RP];          // row=lane, conflict-free
            float a1 = atBase[(j0 + 1) * RP];
            unsigned long long A0 = pk2(a0, a0);
            unsigned long long A1 = pk2(a1, a1);

            // F row j0: all 16 floats (4x LDS.128 broadcast)
            {
                const ulonglong2* fp = (const ulonglong2*)(fT + j0 * DD);
                ulonglong2 u0 = fp[0], u1 = fp[1], u2 = fp[2], u3 = fp[3];
                af[0] = fma2(A0, u0.x, af[0]);
                af[1] = fma2(A0, u0.y, af[1]);
                af[2] = fma2(A0, u1.x, af[2]);
                af[3] = fma2(A0, u1.y, af[3]);
                af[4] = fma2(A0, u2.x, af[4]);
                af[5] = fma2(A0, u2.y, af[5]);
                af[6] = fma2(A0, u3.x, af[6]);
                af[7] = fma2(A0, u3.y, af[7]);
            }
            // F row j0+1
            {
                const ulonglong2* fp = (const ulonglong2*)(fT + (j0 + 1) * DD);
                ulonglong2 u0 = fp[0], u1 = fp[1], u2 = fp[2], u3 = fp[3];
                af[0] = fma2(A1, u0.x, af[0]);
                af[1] = fma2(A1, u0.y, af[1]);
                af[2] = fma2(A1, u1.x, af[2]);
                af[3] = fma2(A1, u1.y, af[3]);
                af[4] = fma2(A1, u2.x, af[4]);
                af[5] = fma2(A1, u2.y, af[5]);
                af[6] = fma2(A1, u3.x, af[6]);
                af[7] = fma2(A1, u3.y, af[7]);
            }

            unsigned long long p = pk2(a0, a1);
            deg2 = add2(deg2, p);
            ss2  = fma2(p, p, ss2);
        }
        __syncwarp();
    }

    // dot_n partial = af . f_n  (f_n from global, full fp32, L2-resident)
    {
        const ulonglong2* fnp =
            (const ulonglong2*)(Fm + ((size_t)b * NN + n0 + lane) * DD);
        ulonglong2 v0 = fnp[0], v1 = fnp[1], v2 = fnp[2], v3 = fnp[3];
        unsigned long long acc = 0ull;
        acc = fma2(af[0], v0.x, acc);
        acc = fma2(af[1], v0.y, acc);
        acc = fma2(af[2], v1.x, acc);
        acc = fma2(af[3], v1.y, acc);
        acc = fma2(af[4], v2.x, acc);
        acc = fma2(af[5], v2.y, acc);
        acc = fma2(af[6], v3.x, acc);
        acc = fma2(af[7], v3.y, acc);
        float ax, ay; upk2(acc, ax, ay);
        float dot = ax + ay;
        float dA, dB; upk2(deg2, dA, dB);
        float deg = dA + dB;
        float sA, sB; upk2(ss2, sA, sB);
        float ss = sA + sB;
        sDeg[lane * 9 + w] = deg;
        sC[lane * 9 + w]   = 0.1f * ss - 0.2f * dot;
    }
    __syncthreads();

    if (w == 0) {
        const int row = lane;
        float deg = 0.0f, c = 0.0f;
        #pragma unroll
        for (int k = 0; k < WARPS; k++) {
            deg += sDeg[row * 9 + k];
            c   += sC[row * 9 + k];
        }
        g_deg[b][n0 + row][half] = deg;

        const float* fn = Fm + ((size_t)b * NN + n0 + row) * DD;
        float nrm = 0.0f;
        #pragma unroll
        for (int d = 0; d < DD; d++) nrm += fn[d] * fn[d];

        const float invN2 = 1.0f / ((float)NN * (float)NN);
        float v = (c + 0.2f * deg * nrm) * invN2;

        #pragma unroll
        for (int o = 16; o > 0; o >>= 1)
            v += __shfl_down_sync(0xFFFFFFFFu, v, o);
        if (lane == 0) atomicAdd(&out[b], v);
    }
}

__global__ void __launch_bounds__(256, 8)
log_pass_kernel(float* __restrict__ out) {
    const int b   = blockIdx.x;
    const int tid = threadIdx.x;
    float s = 0.0f;
    #pragma unroll
    for (int i = 0; i < NN / 256; i++) {
        int n = tid + i * 256;
        s += logf(g_deg[b][n][0] + g_deg[b][n][1] + 1e-12f);
    }
    __shared__ float red[8];
    #pragma unroll
    for (int o = 16; o > 0; o >>= 1)
        s += __shfl_down_sync(0xFFFFFFFFu, s, o);
    if ((tid & 31) == 0) red[tid >> 5] = s;
    __syncthreads();
    if (tid < 8) {
        float v = red[tid];
        #pragma unroll
        for (int o = 4; o > 0; o >>= 1)
            v += __shfl_down_sync(0xFFu, v, o);
        if (tid == 0) atomicAdd(&out[b], -0.1f * v / (float)NN);
    }
}

extern "C" void kernel_launch(void* const* d_in, const int* in_sizes, int n_in,
                              void* d_out, int out_size) {
    const float* A  = (const float*)d_in[0];   // [64,1024,1024]
    const float* Fm = (const float*)d_in[1];   // [64,1024,16]
    float* out      = (float*)d_out;           // [64]

    cudaFuncSetAttribute(graph_loss_main,
                         cudaFuncAttributeMaxDynamicSharedMemorySize, SMEM_BYTES);

    zero_out_kernel<<<1, 64>>>(out);

    dim3 grid(NN / ROWS, 2, BATCH);            // (32, 2, 64)
    graph_loss_main<<<grid, THREADS, SMEM_BYTES>>>(A, Fm, out);

    log_pass_kernel<<<BATCH, 256>>>(out);
}

// round 6
// speedup vs baseline: 2.2309x; 2.2309x over previous
#include <cuda_runtime.h>
#include <cuda_bf16.h>
#include <cstdint>
#include <math.h>

#define BATCH 64
#define NN    1024
#define DD    16
#define THREADS 256

#define MROWS 128            // rows per CTA (8 warps x 16 rows)
#define KH    512            // K columns per CTA (half of N)
#define SLAB  16             // k per pipeline step
#define NS    (KH / SLAB)    // 32 steps

#define APITCH 48            // A tile row pitch bytes (16-aligned, conflict-free ldmatrix)
#define BPITCH 48            // B tile row pitch bytes

__device__ float g_deg[BATCH][NN][2];          // per-(b,n) degree halves
__device__ float g_part[BATCH][2][NN / MROWS]; // per-CTA loss partials

// ---------------- helpers ----------------
__device__ __forceinline__ unsigned smem_u32(const void* p) {
    unsigned a;
    asm("{ .reg .u64 t; cvta.to.shared.u64 t, %1; cvt.u32.u64 %0, t; }" : "=r"(a) : "l"(p));
    return a;
}
__device__ __forceinline__ unsigned long long pk2(float a, float b) {
    unsigned long long r;
    asm("mov.b64 %0, {%1, %2};" : "=l"(r) : "f"(a), "f"(b));
    return r;
}
__device__ __forceinline__ void upk2(unsigned long long v, float& a, float& b) {
    asm("mov.b64 {%0, %1}, %2;" : "=f"(a), "=f"(b) : "l"(v));
}
__device__ __forceinline__ unsigned long long fma2(unsigned long long a,
                                                   unsigned long long b,
                                                   unsigned long long c) {
    unsigned long long d;
    asm("fma.rn.f32x2 %0, %1, %2, %3;" : "=l"(d) : "l"(a), "l"(b), "l"(c));
    return d;
}
__device__ __forceinline__ unsigned cvt_bf16x2(float lo, float hi) {
    unsigned r;  // memory layout: [lo, hi]
    asm("cvt.rn.satfinite.bf16x2.f32 %0, %1, %2;" : "=r"(r) : "f"(hi), "f"(lo));
    return r;
}
__device__ __forceinline__ unsigned long long pack4(float4 v) {
    unsigned h0 = cvt_bf16x2(v.x, v.y);
    unsigned h1 = cvt_bf16x2(v.z, v.w);
    return (unsigned long long)h0 | ((unsigned long long)h1 << 32);
}
__device__ __forceinline__ void ldsm4(unsigned* r, unsigned a) {
    asm volatile("ldmatrix.sync.aligned.m8n8.x4.shared.b16 {%0,%1,%2,%3}, [%4];"
                 : "=r"(r[0]), "=r"(r[1]), "=r"(r[2]), "=r"(r[3]) : "r"(a) : "memory");
}
__device__ __forceinline__ void ldsm4t(unsigned* r, unsigned a) {
    asm volatile("ldmatrix.sync.aligned.m8n8.x4.trans.shared.b16 {%0,%1,%2,%3}, [%4];"
                 : "=r"(r[0]), "=r"(r[1]), "=r"(r[2]), "=r"(r[3]) : "r"(a) : "memory");
}
__device__ __forceinline__ void mma_bf16(float* c, const unsigned* a,
                                         unsigned b0, unsigned b1) {
    asm volatile(
        "mma.sync.aligned.m16n8k16.row.col.f32.bf16.bf16.f32 "
        "{%0,%1,%2,%3}, {%4,%5,%6,%7}, {%8,%9}, {%0,%1,%2,%3};"
        : "+f"(c[0]), "+f"(c[1]), "+f"(c[2]), "+f"(c[3])
        : "r"(a[0]), "r"(a[1]), "r"(a[2]), "r"(a[3]), "r"(b0), "r"(b1));
}

__global__ void __launch_bounds__(THREADS, 4)
graph_loss_main(const float* __restrict__ A, const float* __restrict__ Fm) {
    __shared__ __align__(128) unsigned char sB[KH * BPITCH];         // F half: [k][16 bf16]
    __shared__ __align__(128) unsigned char sA[8 * 16 * APITCH];     // per-warp A tiles
    __shared__ float sRed[16];

    const int rb   = blockIdx.x;
    const int half = blockIdx.y;
    const int b    = blockIdx.z;
    const int n0   = rb * MROWS;
    const int tid  = threadIdx.x;
    const int wid  = tid >> 5;
    const int lane = tid & 31;

    // ---- stage F-half into sB as bf16 [k][16] (48B pitch) ----
    {
        const float4* Fh = (const float4*)(Fm + ((size_t)b * NN + (size_t)half * KH) * DD);
        #pragma unroll
        for (int i = 0; i < (KH * DD / 4) / THREADS; i++) {
            int idx = tid + i * THREADS;       // 0..2047
            int k = idx >> 2, c4 = idx & 3;
            float4 v = Fh[idx];
            *(unsigned long long*)(sB + k * BPITCH + c4 * 8) = pack4(v);
        }
    }
    __syncthreads();

    // ---- per-warp setup ----
    unsigned char* myA = sA + wid * (16 * APITCH);
    const int r8 = lane >> 2;          // 0..7
    const int c4 = lane & 3;           // float4 index within 16-float slab row
    const float* Ap = A + ((size_t)b * NN + n0 + wid * 16 + r8) * NN
                        + (size_t)half * KH + c4 * 4;
    const size_t ROW8 = (size_t)8 * NN;

    unsigned char* sts0 = myA + r8 * APITCH + c4 * 8;
    unsigned char* sts1 = myA + (r8 + 8) * APITCH + c4 * 8;
    const unsigned ldmA = smem_u32(myA) + (lane & 15) * APITCH + (lane >> 4) * 16;
    const unsigned ldmB = smem_u32(sB) + (lane & 15) * BPITCH + (lane >> 4) * 16;

    float c0[4] = {0, 0, 0, 0};   // cols 0-7
    float c1[4] = {0, 0, 0, 0};   // cols 8-15
    float c2[4] = {0, 0, 0, 0};   // cols 16-23 (col16 = deg)
    unsigned long long ss2 = 0ull;
    const unsigned bones = (lane < 4) ? 0x3F803F80u : 0u;  // ones column frag

    float4 p0a = *(const float4*)(Ap);
    float4 p0b = *(const float4*)(Ap + ROW8);
    float4 p1a = *(const float4*)(Ap + SLAB);
    float4 p1b = *(const float4*)(Ap + ROW8 + SLAB);

    #pragma unroll 1
    for (int m = 0; m < NS / 2; m++) {
        // ---- step s = 2m (buffer parity 0) ----
        {
            const int s = 2 * m;
            ss2 = fma2(pk2(p0a.x, p0a.y), pk2(p0a.x, p0a.y), ss2);
            ss2 = fma2(pk2(p0a.z, p0a.w), pk2(p0a.z, p0a.w), ss2);
            ss2 = fma2(pk2(p0b.x, p0b.y), pk2(p0b.x, p0b.y), ss2);
            ss2 = fma2(pk2(p0b.z, p0b.w), pk2(p0b.z, p0b.w), ss2);
            *(unsigned long long*)sts0 = pack4(p0a);
            *(unsigned long long*)sts1 = pack4(p0b);
            if (s + 2 < NS) {
                p0a = *(const float4*)(Ap + (s + 2) * SLAB);
                p0b = *(const float4*)(Ap + ROW8 + (s + 2) * SLAB);
            }
            unsigned af[4], bf[4];
            ldsm4(af, ldmA);
            ldsm4t(bf, ldmB + s * (SLAB * BPITCH));
            mma_bf16(c0, af, bf[0], bf[1]);
            mma_bf16(c1, af, bf[2], bf[3]);
            mma_bf16(c2, af, bones, bones);
        }
        // ---- step s = 2m+1 ----
        {
            const int s = 2 * m + 1;
            ss2 = fma2(pk2(p1a.x, p1a.y), pk2(p1a.x, p1a.y), ss2);
            ss2 = fma2(pk2(p1a.z, p1a.w), pk2(p1a.z, p1a.w), ss2);
            ss2 = fma2(pk2(p1b.x, p1b.y), pk2(p1b.x, p1b.y), ss2);
            ss2 = fma2(pk2(p1b.z, p1b.w), pk2(p1b.z, p1b.w), ss2);
            *(unsigned long long*)sts0 = pack4(p1a);
            *(unsigned long long*)sts1 = pack4(p1b);
            if (s + 2 < NS) {
                p1a = *(const float4*)(Ap + (s + 2) * SLAB);
                p1b = *(const float4*)(Ap + ROW8 + (s + 2) * SLAB);
            }
            unsigned af[4], bf[4];
            ldsm4(af, ldmA);
            ldsm4t(bf, ldmB + s * (SLAB * BPITCH));
            mma_bf16(c0, af, bf[0], bf[1]);
            mma_bf16(c1, af, bf[2], bf[3]);
            mma_bf16(c2, af, bones, bones);
        }
    }

    // ---- epilogue ----
    // C frag: cX[0]=(r1, 2q), cX[1]=(r1, 2q+1), cX[2]=(r1+8, 2q), cX[3]=(r1+8, 2q+1)
    const int q  = lane & 3;
    const int r1 = lane >> 2;                  // 0..7
    const int nrow1 = n0 + wid * 16 + r1;
    const int nrow2 = nrow1 + 8;
    const float* F1 = Fm + ((size_t)b * NN + nrow1) * DD;
    const float* F2 = Fm + ((size_t)b * NN + nrow2) * DD;
    float2 fa1 = *(const float2*)(F1 + 2 * q);
    float2 fb1 = *(const float2*)(F1 + 8 + 2 * q);
    float2 fa2 = *(const float2*)(F2 + 2 * q);
    float2 fb2 = *(const float2*)(F2 + 8 + 2 * q);

    float dot1 = c0[0] * fa1.x + c0[1] * fa1.y + c1[0] * fb1.x + c1[1] * fb1.y;
    float dot2 = c0[2] * fa2.x + c0[3] * fa2.y + c1[2] * fb2.x + c1[3] * fb2.y;
    float nrm1 = fa1.x * fa1.x + fa1.y * fa1.y + fb1.x * fb1.x + fb1.y * fb1.y;
    float nrm2 = fa2.x * fa2.x + fa2.y * fa2.y + fb2.x * fb2.x + fb2.y * fb2.y;

    #pragma unroll
    for (int o = 1; o <= 2; o <<= 1) {
        dot1 += __shfl_xor_sync(0xFFFFFFFFu, dot1, o);
        dot2 += __shfl_xor_sync(0xFFFFFFFFu, dot2, o);
        nrm1 += __shfl_xor_sync(0xFFFFFFFFu, nrm1, o);
        nrm2 += __shfl_xor_sync(0xFFFFFFFFu, nrm2, o);
    }

    float v = 0.0f;
    if (q == 0) {
        float deg1 = c2[0], deg2 = c2[2];      // col 16 of ones-block
        g_deg[b][nrow1][half] = deg1;
        g_deg[b][nrow2][half] = deg2;
        v = (deg1 * nrm1 - dot1) + (deg2 * nrm2 - dot2);
    }
    float ssa, ssb;
    upk2(ss2, ssa, ssb);
    float ssv = ssa + ssb;
    #pragma unroll
    for (int o = 16; o > 0; o >>= 1) {
        v   += __shfl_down_sync(0xFFFFFFFFu, v, o);
        ssv += __shfl_down_sync(0xFFFFFFFFu, ssv, o);
    }
    if (lane == 0) { sRed[wid] = ssv; sRed[8 + wid] = v; }
    __syncthreads();
    if (tid == 0) {
        float ss = 0.0f, sm = 0.0f;
        #pragma unroll
        for (int k = 0; k < 8; k++) { ss += sRed[k]; sm += sRed[8 + k]; }
        const float invN2 = 1.0f / ((float)NN * (float)NN);
        g_part[b][half][rb] = (0.2f * sm + 0.1f * ss) * invN2;
    }
}

__global__ void __launch_bounds__(256, 8)
finalize_kernel(float* __restrict__ out) {
    const int b   = blockIdx.x;
    const int tid = threadIdx.x;
    float s = 0.0f;
    #pragma unroll
    for (int i = 0; i < NN / 256; i++) {
        int n = tid + i * 256;
        s += logf(g_deg[b][n][0] + g_deg[b][n][1] + 1e-12f);
    }
    __shared__ float red[8];
    #pragma unroll
    for (int o = 16; o > 0; o >>= 1)
        s += __shfl_down_sync(0xFFFFFFFFu, s, o);
    if ((tid & 31) == 0) red[tid >> 5] = s;
    __syncthreads();
    if (tid == 0) {
        float lg = 0.0f;
        #pragma unroll
        for (int k = 0; k < 8; k++) lg += red[k];
        float ps = 0.0f;
        #pragma unroll
        for (int h = 0; h < 2; h++)
            #pragma unroll
            for (int rbl = 0; rbl < NN / MROWS; rbl++) ps += g_part[b][h][rbl];
        out[b] = ps - 0.1f * lg / (float)NN;
    }
}

extern "C" void kernel_launch(void* const* d_in, const int* in_sizes, int n_in,
                              void* d_out, int out_size) {
    const float* A  = (const float*)d_in[0];   // [64,1024,1024]
    const float* Fm = (const float*)d_in[1];   // [64,1024,16]
    float* out      = (float*)d_out;           // [64]

    dim3 grid(NN / MROWS, 2, BATCH);           // (8, 2, 64) = 1024 CTAs
    graph_loss_main<<<grid, THREADS>>>(A, Fm);
    finalize_kernel<<<BATCH, 256>>>(out);
}